// round 10
// baseline (speedup 1.0000x reference)
#include <cuda_runtime.h>

#define BATCH 48
#define HH 128
#define WW 128
#define HW 16384

// ---------------- scratch (device globals; no allocation) ----------------
__device__ float g_in0[BATCH * 16 * HW];   // conv1x1(high) output
__device__ float g_v[BATCH * 16 * HW];     // branch conv output (pre-GN "high")
__device__ float g_u[BATCH * 16 * HW];     // conv1x1(low) output (pre-GN "low")
__device__ float g_z[BATCH * 16 * HW];     // ref conv output (pre-GN)
__device__ float g_seg[BATCH * HW];        // seg logits at 128x128
__device__ float g_part_high[BATCH * 32 * 2];
__device__ float g_part_low[BATCH * 16 * 4];
__device__ float g_part_z[BATCH * 32 * 4];

__device__ __forceinline__ float mish_f(float x) {
    if (x > 20.f) return x;
    float e = __expf(x);
    float n = e * (e + 2.f);
    return x * n / (n + 2.f);
}

__device__ __forceinline__ float tf32r(float x) {
    unsigned u;
    asm("cvt.rna.tf32.f32 %0, %1;" : "=r"(u) : "f"(x));
    return __uint_as_float(u);
}

// m16n8k8 tf32 mma, fp32 accumulate (row.col)
__device__ __forceinline__ void mma8(float& d0, float& d1, float& d2, float& d3,
                                     float a0, float a1, float a2, float a3,
                                     float b0, float b1) {
    asm("mma.sync.aligned.m16n8k8.row.col.f32.tf32.tf32.f32 "
        "{%0,%1,%2,%3}, {%4,%5,%6,%7}, {%8,%9}, {%0,%1,%2,%3};"
        : "+f"(d0), "+f"(d1), "+f"(d2), "+f"(d3)
        : "r"(__float_as_uint(a0)), "r"(__float_as_uint(a1)),
          "r"(__float_as_uint(a2)), "r"(__float_as_uint(a3)),
          "r"(__float_as_uint(b0)), "r"(__float_as_uint(b1)));
}

// ---------------- K1: in0 = conv1x1(high, Wc0)  (32 -> 16) ----------------
__global__ __launch_bounds__(256) void k1_conv1x1_high(
    const float* __restrict__ high, const float* __restrict__ Wc0) {
    __shared__ float sw[512];
    int t = threadIdx.x;
    for (int i = t; i < 512; i += 256) sw[i] = Wc0[i];
    __syncthreads();
    int b = blockIdx.y;
    int p0 = blockIdx.x * 1024;
    const float* hb = high + (size_t)b * 32 * HW + p0 + t;
    float* ob = g_in0 + (size_t)b * 16 * HW + p0 + t;
    float acc[4][16];
#pragma unroll
    for (int i = 0; i < 4; i++)
#pragma unroll
        for (int o = 0; o < 16; o++) acc[i][o] = 0.f;
    for (int c = 0; c < 32; c++) {
        float x0 = hb[c * HW], x1 = hb[c * HW + 256];
        float x2 = hb[c * HW + 512], x3 = hb[c * HW + 768];
#pragma unroll
        for (int o = 0; o < 16; o++) {
            float w = sw[o * 32 + c];
            acc[0][o] += x0 * w; acc[1][o] += x1 * w;
            acc[2][o] += x2 * w; acc[3][o] += x3 * w;
        }
    }
#pragma unroll
    for (int o = 0; o < 16; o++) {
        ob[o * HW] = acc[0][o]; ob[o * HW + 256] = acc[1][o];
        ob[o * HW + 512] = acc[2][o]; ob[o * HW + 768] = acc[3][o];
    }
}

// ---------------- K2: branch convs via tf32 mma (implicit GEMM) ----------
// k-remap: k = tap*8 + q  (q = channel within branch). Chunk = one tap,
// all addresses are base + compile-time constants after full unroll.
__global__ __launch_bounds__(128) void k2_branch(
    const float* __restrict__ Wc1, const float* __restrict__ Wc2) {
    __shared__ float sx[5760];       // phase1: [8][18][34], phase2: [8][20][36]
    __shared__ float swt[2][8 * 73]; // permuted tf32 weights, pitch 73
    __shared__ float wred[8];
    int t = threadIdx.x;
    int b = blockIdx.y;
    int tile = blockIdx.x;
    int x0 = (tile & 3) * 32, y0 = (tile >> 2) * 16;
    for (int i = t; i < 8 * 73; i += 128) {
        int o = i / 73, j = i - o * 73;
        float w1 = 0.f, w2 = 0.f;
        if (j < 72) {
            int tap = j >> 3, q = j & 7;        // k = tap*8+q  <->  W[o][q][tap]
            w1 = tf32r(Wc1[o * 72 + q * 9 + tap]);
            w2 = tf32r(Wc2[o * 72 + q * 9 + tap]);
        }
        swt[0][i] = w1; swt[1][i] = w2;
    }
    int lane = t & 31, w4 = t >> 5;
    int grp = lane >> 2, qid = lane & 3;
    const float* in0b = g_in0 + (size_t)b * 16 * HW;
    float* vb = g_v + (size_t)b * 16 * HW;
    float ls1 = 0.f, ls2 = 0.f;

    // ---- phase 1: channels 0..7, dilation 1, halo 1 (18 x 34) ----
    for (int i = t; i < 8 * 18 * 34; i += 128) {
        int c = i / 612; int rem = i - c * 612;
        int yy = rem / 34; int xx = rem - yy * 34;
        int gy = y0 - 1 + yy, gx = x0 - 1 + xx;
        float val = 0.f;
        if ((unsigned)gy < 128u && (unsigned)gx < 128u)
            val = in0b[c * HW + gy * WW + gx];
        sx[i] = tf32r(val);
    }
    __syncthreads();
    {
        float acc[16][2];
        float dz0 = 0.f, dz1 = 0.f;
#pragma unroll
        for (int g = 0; g < 16; g++) { acc[g][0] = 0.f; acc[g][1] = 0.f; }
        const float* pB = sx + w4 * 4 * 34 + grp + qid * 612;  // qid = channel q
        const float* pW = &swt[0][grp * 73 + qid];
#pragma unroll
        for (int tap = 0; tap < 9; tap++) {
            const int ky = tap / 3, kx = tap - ky * 3;
            const int coff = ky * 34 + kx;                     // compile-time
            float a0 = pW[tap * 8];
            float a2 = pW[tap * 8 + 4];
#pragma unroll
            for (int g = 0; g < 16; g++) {
                const int imm = coff + (g >> 2) * 34 + (g & 3) * 8;
                mma8(acc[g][0], acc[g][1], dz0, dz1, a0, 0.f, a2, 0.f,
                     pB[imm], pB[imm + 4 * 612]);
            }
        }
#pragma unroll
        for (int g = 0; g < 16; g++) {
            int gy = y0 + w4 * 4 + (g >> 2);
            int gx = x0 + (g & 3) * 8 + 2 * qid;
            float d0 = acc[g][0], d1 = acc[g][1];
            float2 st; st.x = d0; st.y = d1;
            *(float2*)&vb[grp * HW + gy * WW + gx] = st;
            ls1 += d0 + d1; ls2 += d0 * d0 + d1 * d1;
        }
    }
    __syncthreads();
    // ---- phase 2: channels 8..15, dilation 2, halo 2 (20 x 36) ----
    for (int i = t; i < 8 * 20 * 36; i += 128) {
        int c = i / 720; int rem = i - c * 720;
        int yy = rem / 36; int xx = rem - yy * 36;
        int gy = y0 - 2 + yy, gx = x0 - 2 + xx;
        float val = 0.f;
        if ((unsigned)gy < 128u && (unsigned)gx < 128u)
            val = in0b[(c + 8) * HW + gy * WW + gx];
        sx[i] = tf32r(val);
    }
    __syncthreads();
    {
        float acc[16][2];
        float dz0 = 0.f, dz1 = 0.f;
#pragma unroll
        for (int g = 0; g < 16; g++) { acc[g][0] = 0.f; acc[g][1] = 0.f; }
        const float* pB = sx + w4 * 4 * 36 + grp + qid * 720;
        const float* pW = &swt[1][grp * 73 + qid];
#pragma unroll
        for (int tap = 0; tap < 9; tap++) {
            const int ky = tap / 3, kx = tap - ky * 3;
            const int coff = 2 * ky * 36 + 2 * kx;             // dilation 2
            float a0 = pW[tap * 8];
            float a2 = pW[tap * 8 + 4];
#pragma unroll
            for (int g = 0; g < 16; g++) {
                const int imm = coff + (g >> 2) * 36 + (g & 3) * 8;
                mma8(acc[g][0], acc[g][1], dz0, dz1, a0, 0.f, a2, 0.f,
                     pB[imm], pB[imm + 4 * 720]);
            }
        }
#pragma unroll
        for (int g = 0; g < 16; g++) {
            int gy = y0 + w4 * 4 + (g >> 2);
            int gx = x0 + (g & 3) * 8 + 2 * qid;
            float d0 = acc[g][0], d1 = acc[g][1];
            float2 st; st.x = d0; st.y = d1;
            *(float2*)&vb[(grp + 8) * HW + gy * WW + gx] = st;
            ls1 += d0 + d1; ls2 += d0 * d0 + d1 * d1;
        }
    }
    // ---- deterministic reduce ----
#pragma unroll
    for (int o = 16; o; o >>= 1) {
        ls1 += __shfl_xor_sync(0xffffffffu, ls1, o);
        ls2 += __shfl_xor_sync(0xffffffffu, ls2, o);
    }
    if (lane == 0) { wred[w4] = ls1; wred[4 + w4] = ls2; }
    __syncthreads();
    if (t == 0) {
        g_part_high[(b * 32 + tile) * 2 + 0] = wred[0] + wred[1] + wred[2] + wred[3];
        g_part_high[(b * 32 + tile) * 2 + 1] = wred[4] + wred[5] + wred[6] + wred[7];
    }
}

// ---------------- K3: u = conv1x1(low, Wlow) (24 -> 16), + GN-low partials
__global__ __launch_bounds__(256) void k3_low(
    const float* __restrict__ low, const float* __restrict__ Wlow) {
    __shared__ float sw[384];
    __shared__ float red[256];
    int t = threadIdx.x;
    int b = blockIdx.y;
    int p0 = blockIdx.x * 1024;
    for (int i = t; i < 384; i += 256) sw[i] = Wlow[i];
    __syncthreads();
    const float* lb = low + (size_t)b * 24 * HW + p0 + t;
    float* ub = g_u + (size_t)b * 16 * HW + p0 + t;
    float acc[4][16];
#pragma unroll
    for (int i = 0; i < 4; i++)
#pragma unroll
        for (int o = 0; o < 16; o++) acc[i][o] = 0.f;
    for (int c = 0; c < 24; c++) {
        float x0 = lb[c * HW], x1 = lb[c * HW + 256];
        float x2 = lb[c * HW + 512], x3 = lb[c * HW + 768];
#pragma unroll
        for (int o = 0; o < 16; o++) {
            float w = sw[o * 24 + c];
            acc[0][o] += x0 * w; acc[1][o] += x1 * w;
            acc[2][o] += x2 * w; acc[3][o] += x3 * w;
        }
    }
    float sv[4] = {0.f, 0.f, 0.f, 0.f};
#pragma unroll
    for (int o = 0; o < 16; o++) {
        float v0 = acc[0][o], v1 = acc[1][o], v2 = acc[2][o], v3 = acc[3][o];
        ub[o * HW] = v0; ub[o * HW + 256] = v1;
        ub[o * HW + 512] = v2; ub[o * HW + 768] = v3;
        int g = (o >> 3) * 2;
        sv[g] += v0 + v1 + v2 + v3;
        sv[g + 1] += v0 * v0 + v1 * v1 + v2 * v2 + v3 * v3;
    }
#pragma unroll
    for (int j = 0; j < 4; j++) {
        red[t] = sv[j]; __syncthreads();
        for (int s = 128; s > 0; s >>= 1) { if (t < s) red[t] += red[t + s]; __syncthreads(); }
        if (t == 0) g_part_low[(b * 16 + blockIdx.x) * 4 + j] = red[0];
        __syncthreads();
    }
}

// ---------------- K5: (inlined GN stats) + mish fuse + conv3x3 via tf32 mma
__global__ __launch_bounds__(128) void k5_ref(
    const float* __restrict__ Wref,
    const float* __restrict__ gbn, const float* __restrict__ bbn,
    const float* __restrict__ glow, const float* __restrict__ blow) {
    __shared__ float sr[9792];       // [16][18][34]
    __shared__ float sw5[16 * 145];  // permuted tf32 weights, pitch 145
    __shared__ float sa1[16], sa2[16], sa3[16];
    __shared__ float wred[16];
    int t = threadIdx.x;
    int b = blockIdx.y;
    int tile = blockIdx.x;
    int x0 = (tile & 3) * 32, y0 = (tile >> 2) * 16;
    for (int i = t; i < 16 * 145; i += 128) {
        int o = i / 145, j = i - o * 145;
        float w = 0.f;
        if (j < 144) {
            int c = j >> 3, q = j & 7;           // k = c*8+q
            int tap = c >> 1, half = c & 1;      // ci = half*8+q
            w = tf32r(Wref[o * 144 + (half * 8 + q) * 9 + tap]);
        }
        sw5[i] = w;
    }
    // --- inlined stats (was k4): warp 0 reduces partials ---
    if (t < 32) {
        float h1 = g_part_high[(b * 32 + t) * 2 + 0];
        float h2 = g_part_high[(b * 32 + t) * 2 + 1];
#pragma unroll
        for (int o = 16; o; o >>= 1) {
            h1 += __shfl_xor_sync(0xffffffffu, h1, o);
            h2 += __shfl_xor_sync(0xffffffffu, h2, o);
        }
        float l[4];
#pragma unroll
        for (int j = 0; j < 4; j++) {
            float v = (t < 16) ? g_part_low[(b * 16 + t) * 4 + j] : 0.f;
#pragma unroll
            for (int o = 16; o; o >>= 1) v += __shfl_xor_sync(0xffffffffu, v, o);
            l[j] = v;
        }
        if (t < 16) {
            int c = t, g = c >> 3;
            float nH = 16.f * HW, nL = 8.f * HW;
            float mH = h1 / nH;
            float rH = rsqrtf(h2 / nH - mH * mH + 1e-5f);
            float mL = l[2 * g] / nL;
            float rL = rsqrtf(l[2 * g + 1] / nL - mL * mL + 1e-5f);
            float a1 = rH * gbn[c], a2 = rL * glow[c];
            sa1[c] = a1; sa2[c] = a2;
            sa3[c] = bbn[c] + blow[c] - mH * a1 - mL * a2;
        }
    }
    __syncthreads();
    const float* vb = g_v + (size_t)b * 16 * HW;
    const float* ub = g_u + (size_t)b * 16 * HW;
    for (int i = t; i < 9792; i += 128) {
        int c = i / 612; int rem = i - c * 612;
        int yy = rem / 34; int xx = rem - yy * 34;
        int gy = y0 - 1 + yy, gx = x0 - 1 + xx;
        float val = 0.f;
        if ((unsigned)gy < 128u && (unsigned)gx < 128u) {
            int off = c * HW + gy * WW + gx;
            val = mish_f(vb[off] * sa1[c] + ub[off] * sa2[c] + sa3[c]);
        }
        sr[i] = tf32r(val);
    }
    __syncthreads();
    int lane = t & 31, w4 = t >> 5;
    int grp = lane >> 2, qid = lane & 3;
    float acc[16][4];
#pragma unroll
    for (int g = 0; g < 16; g++) {
        acc[g][0] = 0.f; acc[g][1] = 0.f; acc[g][2] = 0.f; acc[g][3] = 0.f;
    }
    const float* pB = sr + w4 * 4 * 34 + grp + qid * 612;
    const float* pW = sw5 + grp * 145 + qid;
#pragma unroll
    for (int c = 0; c < 18; c++) {
        const int tap = c >> 1, half = c & 1;
        const int ky = tap / 3, kx = tap - ky * 3;
        const int coff = half * 8 * 612 + ky * 34 + kx;        // compile-time
        float a0 = pW[c * 8];
        float a2 = pW[c * 8 + 4];
        float a1 = pW[c * 8 + 8 * 145];
        float a3 = pW[c * 8 + 8 * 145 + 4];
#pragma unroll
        for (int g = 0; g < 16; g++) {
            const int imm = coff + (g >> 2) * 34 + (g & 3) * 8;
            mma8(acc[g][0], acc[g][1], acc[g][2], acc[g][3],
                 a0, a1, a2, a3, pB[imm], pB[imm + 4 * 612]);
        }
    }
    float* zb = g_z + (size_t)b * 16 * HW;
    float sv[4] = {0.f, 0.f, 0.f, 0.f};
#pragma unroll
    for (int g = 0; g < 16; g++) {
        int gy = y0 + w4 * 4 + (g >> 2);
        int gx = x0 + (g & 3) * 8 + 2 * qid;
        float d0 = acc[g][0], d1 = acc[g][1], d2 = acc[g][2], d3 = acc[g][3];
        float2 s0; s0.x = d0; s0.y = d1;
        float2 s1; s1.x = d2; s1.y = d3;
        *(float2*)&zb[grp * HW + gy * WW + gx] = s0;
        *(float2*)&zb[(grp + 8) * HW + gy * WW + gx] = s1;
        sv[0] += d0 + d1; sv[1] += d0 * d0 + d1 * d1;
        sv[2] += d2 + d3; sv[3] += d2 * d2 + d3 * d3;
    }
#pragma unroll
    for (int o = 16; o; o >>= 1) {
#pragma unroll
        for (int j = 0; j < 4; j++) sv[j] += __shfl_xor_sync(0xffffffffu, sv[j], o);
    }
    if (lane == 0) {
#pragma unroll
        for (int j = 0; j < 4; j++) wred[w4 * 4 + j] = sv[j];
    }
    __syncthreads();
    if (t == 0) {
#pragma unroll
        for (int j = 0; j < 4; j++)
            g_part_z[(b * 32 + tile) * 4 + j] =
                wred[j] + wred[4 + j] + wred[8 + j] + wred[12 + j];
    }
}

// ---------------- K7: (inlined GN-z stats) + seg = conv1x1(mish(GN(z)), Wseg)
__global__ __launch_bounds__(256) void k7_seg(
    const float* __restrict__ gref, const float* __restrict__ bref,
    const float* __restrict__ Wseg) {
    __shared__ float sa[16], sb[16], sws[16];
    int t = threadIdx.x, b = blockIdx.y;
    int p = blockIdx.x * 256 + t;
    if (t < 32) {
        float l[4];
#pragma unroll
        for (int j = 0; j < 4; j++) {
            float v = g_part_z[(b * 32 + t) * 4 + j];
#pragma unroll
            for (int o = 16; o; o >>= 1) v += __shfl_xor_sync(0xffffffffu, v, o);
            l[j] = v;
        }
        if (t < 16) {
            int g = t >> 3;
            float n = 8.f * HW;
            float m = l[2 * g] / n;
            float r = rsqrtf(l[2 * g + 1] / n - m * m + 1e-5f);
            float a = r * gref[t];
            sa[t] = a; sb[t] = bref[t] - m * a; sws[t] = Wseg[t];
        }
    }
    __syncthreads();
    const float* zb = g_z + (size_t)b * 16 * HW + p;
    float acc = 0.f;
#pragma unroll
    for (int c = 0; c < 16; c++) {
        float zn = zb[c * HW] * sa[c] + sb[c];
        acc += mish_f(zn) * sws[c];
    }
    g_seg[b * HW + p] = acc;
}

// ---------------- K8: bilinear 128->512 + sigmoid ----------------
__global__ __launch_bounds__(256) void k8_up(float4* __restrict__ out) {
    int idx4 = blockIdx.x * 256 + threadIdx.x;
    int idx = idx4 * 4;
    int b = idx >> 18;
    int rem = idx & 262143;
    int oy = rem >> 9, ox0 = rem & 511;
    float sy = (oy + 0.5f) * 0.25f - 0.5f;
    sy = fminf(fmaxf(sy, 0.f), 127.f);
    int y0 = (int)sy;
    float fy = sy - y0;
    int y1 = min(y0 + 1, 127);
    const float* s = g_seg + b * HW;
    const float* r0 = s + y0 * 128;
    const float* r1 = s + y1 * 128;
    float4 o4;
    float res[4];
#pragma unroll
    for (int j = 0; j < 4; j++) {
        int ox = ox0 + j;
        float sx = (ox + 0.5f) * 0.25f - 0.5f;
        sx = fminf(fmaxf(sx, 0.f), 127.f);
        int x0 = (int)sx;
        float fx = sx - x0;
        int x1 = min(x0 + 1, 127);
        float top = r0[x0] + (r0[x1] - r0[x0]) * fx;
        float bot = r1[x0] + (r1[x1] - r1[x0]) * fx;
        float v = top + (bot - top) * fy;
        res[j] = 1.f / (1.f + __expf(-v));
    }
    o4.x = res[0]; o4.y = res[1]; o4.z = res[2]; o4.w = res[3];
    out[idx4] = o4;
}

// ---------------- launch ----------------
extern "C" void kernel_launch(void* const* d_in, const int* in_sizes, int n_in,
                              void* d_out, int out_size) {
    (void)in_sizes; (void)n_in; (void)out_size;
    const float* low  = (const float*)d_in[0];
    const float* high = (const float*)d_in[1];
    const float* Wc0  = (const float*)d_in[2];
    const float* Wc1  = (const float*)d_in[3];
    const float* Wc2  = (const float*)d_in[4];
    const float* gbn  = (const float*)d_in[5];
    const float* bbn  = (const float*)d_in[6];
    const float* Wlow = (const float*)d_in[7];
    const float* glow = (const float*)d_in[8];
    const float* blow = (const float*)d_in[9];
    const float* Wref = (const float*)d_in[10];
    const float* gref = (const float*)d_in[11];
    const float* bref = (const float*)d_in[12];
    const float* Wseg = (const float*)d_in[13];
    float* out = (float*)d_out;

    k1_conv1x1_high<<<dim3(16, 48), 256>>>(high, Wc0);
    k2_branch<<<dim3(32, 48), 128>>>(Wc1, Wc2);
    k3_low<<<dim3(16, 48), 256>>>(low, Wlow);
    k5_ref<<<dim3(32, 48), 128>>>(Wref, gbn, bbn, glow, blow);   // launch #4 -> profiled
    k7_seg<<<dim3(64, 48), 256>>>(gref, bref, Wseg);
    k8_up<<<12288, 256>>>((float4*)out);
}

// round 13
// speedup vs baseline: 1.2867x; 1.2867x over previous
#include <cuda_runtime.h>

#define BATCH 48
#define HH 128
#define WW 128
#define HW 16384

// ---------------- scratch (device globals; no allocation) ----------------
__device__ float g_in0[BATCH * 16 * HW];   // conv1x1(high) output
__device__ float g_v[BATCH * 16 * HW];     // branch conv output (pre-GN "high")
__device__ float g_u[BATCH * 16 * HW];     // conv1x1(low) output (pre-GN "low")
__device__ float g_z[BATCH * 16 * HW];     // ref conv output (pre-GN)
__device__ float g_seg[BATCH * HW];        // seg logits at 128x128
__device__ float g_part_high[BATCH * 32 * 2];
__device__ float g_part_low[BATCH * 16 * 4];
__device__ float g_part_z[BATCH * 32 * 4];

__device__ __forceinline__ float mish_f(float x) {
    if (x > 20.f) return x;
    float e = __expf(x);
    float n = e * (e + 2.f);
    return x * n / (n + 2.f);
}

__device__ __forceinline__ float tf32r(float x) {
    unsigned u;
    asm("cvt.rna.tf32.f32 %0, %1;" : "=r"(u) : "f"(x));
    return __uint_as_float(u);
}

// m16n8k8 tf32 mma, fp32 accumulate (row.col)
__device__ __forceinline__ void mma8(float& d0, float& d1, float& d2, float& d3,
                                     float a0, float a1, float a2, float a3,
                                     float b0, float b1) {
    asm("mma.sync.aligned.m16n8k8.row.col.f32.tf32.tf32.f32 "
        "{%0,%1,%2,%3}, {%4,%5,%6,%7}, {%8,%9}, {%0,%1,%2,%3};"
        : "+f"(d0), "+f"(d1), "+f"(d2), "+f"(d3)
        : "r"(__float_as_uint(a0)), "r"(__float_as_uint(a1)),
          "r"(__float_as_uint(a2)), "r"(__float_as_uint(a3)),
          "r"(__float_as_uint(b0)), "r"(__float_as_uint(b1)));
}

// ---------------- K1: in0 = conv1x1(high, Wc0)  (32 -> 16) ----------------
__global__ __launch_bounds__(256) void k1_conv1x1_high(
    const float* __restrict__ high, const float* __restrict__ Wc0) {
    __shared__ float sw[512];
    int t = threadIdx.x;
    for (int i = t; i < 512; i += 256) sw[i] = Wc0[i];
    __syncthreads();
    int b = blockIdx.y;
    int p0 = blockIdx.x * 1024;
    const float* hb = high + (size_t)b * 32 * HW + p0 + t;
    float* ob = g_in0 + (size_t)b * 16 * HW + p0 + t;
    float acc[4][16];
#pragma unroll
    for (int i = 0; i < 4; i++)
#pragma unroll
        for (int o = 0; o < 16; o++) acc[i][o] = 0.f;
    for (int c = 0; c < 32; c++) {
        float x0 = hb[c * HW], x1 = hb[c * HW + 256];
        float x2 = hb[c * HW + 512], x3 = hb[c * HW + 768];
#pragma unroll
        for (int o = 0; o < 16; o++) {
            float w = sw[o * 32 + c];
            acc[0][o] += x0 * w; acc[1][o] += x1 * w;
            acc[2][o] += x2 * w; acc[3][o] += x3 * w;
        }
    }
#pragma unroll
    for (int o = 0; o < 16; o++) {
        ob[o * HW] = acc[0][o]; ob[o * HW + 256] = acc[1][o];
        ob[o * HW + 512] = acc[2][o]; ob[o * HW + 768] = acc[3][o];
    }
}

// ---------------- K2: branch convs via tf32 mma, 8 warps / tile ----------
__global__ __launch_bounds__(256, 4) void k2_branch(
    const float* __restrict__ Wc1, const float* __restrict__ Wc2) {
    __shared__ float sx[5760];       // phase1: [8][18][34], phase2: [8][20][36]
    __shared__ float swt[2][8 * 73]; // permuted tf32 weights, pitch 73
    __shared__ float wred[16];
    int t = threadIdx.x;
    int b = blockIdx.y;
    int tile = blockIdx.x;
    int x0 = (tile & 3) * 32, y0 = (tile >> 2) * 16;
    for (int i = t; i < 8 * 73; i += 256) {
        int o = i / 73, j = i - o * 73;
        float w1 = 0.f, w2 = 0.f;
        if (j < 72) {
            int tap = j >> 3, q = j & 7;        // k = tap*8+q  <->  W[o][q][tap]
            w1 = tf32r(Wc1[o * 72 + q * 9 + tap]);
            w2 = tf32r(Wc2[o * 72 + q * 9 + tap]);
        }
        swt[0][i] = w1; swt[1][i] = w2;
    }
    int lane = t & 31, w8 = t >> 5;            // 8 warps, 2 rows each
    int grp = lane >> 2, qid = lane & 3;
    const float* in0b = g_in0 + (size_t)b * 16 * HW;
    float* vb = g_v + (size_t)b * 16 * HW;
    float ls1 = 0.f, ls2 = 0.f;

    // ---- phase 1: channels 0..7, dilation 1, halo 1 (18 x 34) ----
    for (int i = t; i < 8 * 18 * 34; i += 256) {
        int c = i / 612; int rem = i - c * 612;
        int yy = rem / 34; int xx = rem - yy * 34;
        int gy = y0 - 1 + yy, gx = x0 - 1 + xx;
        float val = 0.f;
        if ((unsigned)gy < 128u && (unsigned)gx < 128u)
            val = in0b[c * HW + gy * WW + gx];
        sx[i] = tf32r(val);
    }
    __syncthreads();
    {
        float acc[8][2];
        float dz0 = 0.f, dz1 = 0.f;
#pragma unroll
        for (int g = 0; g < 8; g++) { acc[g][0] = 0.f; acc[g][1] = 0.f; }
        const float* pB = sx + w8 * 2 * 34 + grp + qid * 612;
        const float* pW = &swt[0][grp * 73 + qid];
#pragma unroll
        for (int tap = 0; tap < 9; tap++) {
            const int ky = tap / 3, kx = tap - ky * 3;
            const int coff = ky * 34 + kx;
            float a0 = pW[tap * 8];
            float a2 = pW[tap * 8 + 4];
#pragma unroll
            for (int g = 0; g < 8; g++) {
                const int imm = coff + (g >> 2) * 34 + (g & 3) * 8;
                mma8(acc[g][0], acc[g][1], dz0, dz1, a0, 0.f, a2, 0.f,
                     pB[imm], pB[imm + 4 * 612]);
            }
        }
#pragma unroll
        for (int g = 0; g < 8; g++) {
            int gy = y0 + w8 * 2 + (g >> 2);
            int gx = x0 + (g & 3) * 8 + 2 * qid;
            float d0 = acc[g][0], d1 = acc[g][1];
            float2 st; st.x = d0; st.y = d1;
            *(float2*)&vb[grp * HW + gy * WW + gx] = st;
            ls1 += d0 + d1; ls2 += d0 * d0 + d1 * d1;
        }
    }
    __syncthreads();
    // ---- phase 2: channels 8..15, dilation 2, halo 2 (20 x 36) ----
    for (int i = t; i < 8 * 20 * 36; i += 256) {
        int c = i / 720; int rem = i - c * 720;
        int yy = rem / 36; int xx = rem - yy * 36;
        int gy = y0 - 2 + yy, gx = x0 - 2 + xx;
        float val = 0.f;
        if ((unsigned)gy < 128u && (unsigned)gx < 128u)
            val = in0b[(c + 8) * HW + gy * WW + gx];
        sx[i] = tf32r(val);
    }
    __syncthreads();
    {
        float acc[8][2];
        float dz0 = 0.f, dz1 = 0.f;
#pragma unroll
        for (int g = 0; g < 8; g++) { acc[g][0] = 0.f; acc[g][1] = 0.f; }
        const float* pB = sx + w8 * 2 * 36 + grp + qid * 720;
        const float* pW = &swt[1][grp * 73 + qid];
#pragma unroll
        for (int tap = 0; tap < 9; tap++) {
            const int ky = tap / 3, kx = tap - ky * 3;
            const int coff = 2 * ky * 36 + 2 * kx;
            float a0 = pW[tap * 8];
            float a2 = pW[tap * 8 + 4];
#pragma unroll
            for (int g = 0; g < 8; g++) {
                const int imm = coff + (g >> 2) * 36 + (g & 3) * 8;
                mma8(acc[g][0], acc[g][1], dz0, dz1, a0, 0.f, a2, 0.f,
                     pB[imm], pB[imm + 4 * 720]);
            }
        }
#pragma unroll
        for (int g = 0; g < 8; g++) {
            int gy = y0 + w8 * 2 + (g >> 2);
            int gx = x0 + (g & 3) * 8 + 2 * qid;
            float d0 = acc[g][0], d1 = acc[g][1];
            float2 st; st.x = d0; st.y = d1;
            *(float2*)&vb[(grp + 8) * HW + gy * WW + gx] = st;
            ls1 += d0 + d1; ls2 += d0 * d0 + d1 * d1;
        }
    }
    // ---- deterministic reduce ----
#pragma unroll
    for (int o = 16; o; o >>= 1) {
        ls1 += __shfl_xor_sync(0xffffffffu, ls1, o);
        ls2 += __shfl_xor_sync(0xffffffffu, ls2, o);
    }
    if (lane == 0) { wred[w8] = ls1; wred[8 + w8] = ls2; }
    __syncthreads();
    if (t == 0) {
        float s1 = 0.f, s2 = 0.f;
#pragma unroll
        for (int w = 0; w < 8; w++) { s1 += wred[w]; s2 += wred[8 + w]; }
        g_part_high[(b * 32 + tile) * 2 + 0] = s1;
        g_part_high[(b * 32 + tile) * 2 + 1] = s2;
    }
}

// ---------------- K3: u = conv1x1(low, Wlow) (24 -> 16), + GN-low partials
__global__ __launch_bounds__(256) void k3_low(
    const float* __restrict__ low, const float* __restrict__ Wlow) {
    __shared__ float sw[384];
    __shared__ float red[256];
    int t = threadIdx.x;
    int b = blockIdx.y;
    int p0 = blockIdx.x * 1024;
    for (int i = t; i < 384; i += 256) sw[i] = Wlow[i];
    __syncthreads();
    const float* lb = low + (size_t)b * 24 * HW + p0 + t;
    float* ub = g_u + (size_t)b * 16 * HW + p0 + t;
    float acc[4][16];
#pragma unroll
    for (int i = 0; i < 4; i++)
#pragma unroll
        for (int o = 0; o < 16; o++) acc[i][o] = 0.f;
    for (int c = 0; c < 24; c++) {
        float x0 = lb[c * HW], x1 = lb[c * HW + 256];
        float x2 = lb[c * HW + 512], x3 = lb[c * HW + 768];
#pragma unroll
        for (int o = 0; o < 16; o++) {
            float w = sw[o * 24 + c];
            acc[0][o] += x0 * w; acc[1][o] += x1 * w;
            acc[2][o] += x2 * w; acc[3][o] += x3 * w;
        }
    }
    float sv[4] = {0.f, 0.f, 0.f, 0.f};
#pragma unroll
    for (int o = 0; o < 16; o++) {
        float v0 = acc[0][o], v1 = acc[1][o], v2 = acc[2][o], v3 = acc[3][o];
        ub[o * HW] = v0; ub[o * HW + 256] = v1;
        ub[o * HW + 512] = v2; ub[o * HW + 768] = v3;
        int g = (o >> 3) * 2;
        sv[g] += v0 + v1 + v2 + v3;
        sv[g + 1] += v0 * v0 + v1 * v1 + v2 * v2 + v3 * v3;
    }
#pragma unroll
    for (int j = 0; j < 4; j++) {
        red[t] = sv[j]; __syncthreads();
        for (int s = 128; s > 0; s >>= 1) { if (t < s) red[t] += red[t + s]; __syncthreads(); }
        if (t == 0) g_part_low[(b * 16 + blockIdx.x) * 4 + j] = red[0];
        __syncthreads();
    }
}

// ---------------- K5: (inlined GN stats) + mish fuse + conv3x3, 8 warps ----
__global__ __launch_bounds__(256, 3) void k5_ref(
    const float* __restrict__ Wref,
    const float* __restrict__ gbn, const float* __restrict__ bbn,
    const float* __restrict__ glow, const float* __restrict__ blow) {
    __shared__ float sr[9792];       // [16][18][34]
    __shared__ float sw5[16 * 145];  // permuted tf32 weights, pitch 145
    __shared__ float sa1[16], sa2[16], sa3[16];
    __shared__ float wred[32];
    int t = threadIdx.x;
    int b = blockIdx.y;
    int tile = blockIdx.x;
    int x0 = (tile & 3) * 32, y0 = (tile >> 2) * 16;
    for (int i = t; i < 16 * 145; i += 256) {
        int o = i / 145, j = i - o * 145;
        float w = 0.f;
        if (j < 144) {
            int c = j >> 3, q = j & 7;           // k = c*8+q
            int tap = c >> 1, half = c & 1;      // ci = half*8+q
            w = tf32r(Wref[o * 144 + (half * 8 + q) * 9 + tap]);
        }
        sw5[i] = w;
    }
    // --- inlined stats: warp 0 reduces partials ---
    if (t < 32) {
        float h1 = g_part_high[(b * 32 + t) * 2 + 0];
        float h2 = g_part_high[(b * 32 + t) * 2 + 1];
#pragma unroll
        for (int o = 16; o; o >>= 1) {
            h1 += __shfl_xor_sync(0xffffffffu, h1, o);
            h2 += __shfl_xor_sync(0xffffffffu, h2, o);
        }
        float l[4];
#pragma unroll
        for (int j = 0; j < 4; j++) {
            float v = (t < 16) ? g_part_low[(b * 16 + t) * 4 + j] : 0.f;
#pragma unroll
            for (int o = 16; o; o >>= 1) v += __shfl_xor_sync(0xffffffffu, v, o);
            l[j] = v;
        }
        if (t < 16) {
            int c = t, g = c >> 3;
            float nH = 16.f * HW, nL = 8.f * HW;
            float mH = h1 / nH;
            float rH = rsqrtf(h2 / nH - mH * mH + 1e-5f);
            float mL = l[2 * g] / nL;
            float rL = rsqrtf(l[2 * g + 1] / nL - mL * mL + 1e-5f);
            float a1 = rH * gbn[c], a2 = rL * glow[c];
            sa1[c] = a1; sa2[c] = a2;
            sa3[c] = bbn[c] + blow[c] - mH * a1 - mL * a2;
        }
    }
    __syncthreads();
    const float* vb = g_v + (size_t)b * 16 * HW;
    const float* ub = g_u + (size_t)b * 16 * HW;
    for (int i = t; i < 9792; i += 256) {
        int c = i / 612; int rem = i - c * 612;
        int yy = rem / 34; int xx = rem - yy * 34;
        int gy = y0 - 1 + yy, gx = x0 - 1 + xx;
        float val = 0.f;
        if ((unsigned)gy < 128u && (unsigned)gx < 128u) {
            int off = c * HW + gy * WW + gx;
            val = mish_f(vb[off] * sa1[c] + ub[off] * sa2[c] + sa3[c]);
        }
        sr[i] = tf32r(val);
    }
    __syncthreads();
    int lane = t & 31, w8 = t >> 5;            // 8 warps, 2 rows each
    int grp = lane >> 2, qid = lane & 3;
    float acc[8][4];
#pragma unroll
    for (int g = 0; g < 8; g++) {
        acc[g][0] = 0.f; acc[g][1] = 0.f; acc[g][2] = 0.f; acc[g][3] = 0.f;
    }
    const float* pB = sr + w8 * 2 * 34 + grp + qid * 612;
    const float* pW = sw5 + grp * 145 + qid;
#pragma unroll
    for (int c = 0; c < 18; c++) {
        const int tap = c >> 1, half = c & 1;
        const int ky = tap / 3, kx = tap - ky * 3;
        const int coff = half * 8 * 612 + ky * 34 + kx;
        float a0 = pW[c * 8];
        float a2 = pW[c * 8 + 4];
        float a1 = pW[c * 8 + 8 * 145];
        float a3 = pW[c * 8 + 8 * 145 + 4];
#pragma unroll
        for (int g = 0; g < 8; g++) {
            const int imm = coff + (g >> 2) * 34 + (g & 3) * 8;
            mma8(acc[g][0], acc[g][1], acc[g][2], acc[g][3],
                 a0, a1, a2, a3, pB[imm], pB[imm + 4 * 612]);
        }
    }
    float* zb = g_z + (size_t)b * 16 * HW;
    float sv[4] = {0.f, 0.f, 0.f, 0.f};
#pragma unroll
    for (int g = 0; g < 8; g++) {
        int gy = y0 + w8 * 2 + (g >> 2);
        int gx = x0 + (g & 3) * 8 + 2 * qid;
        float d0 = acc[g][0], d1 = acc[g][1], d2 = acc[g][2], d3 = acc[g][3];
        float2 s0; s0.x = d0; s0.y = d1;
        float2 s1; s1.x = d2; s1.y = d3;
        *(float2*)&zb[grp * HW + gy * WW + gx] = s0;
        *(float2*)&zb[(grp + 8) * HW + gy * WW + gx] = s1;
        sv[0] += d0 + d1; sv[1] += d0 * d0 + d1 * d1;
        sv[2] += d2 + d3; sv[3] += d2 * d2 + d3 * d3;
    }
#pragma unroll
    for (int o = 16; o; o >>= 1) {
#pragma unroll
        for (int j = 0; j < 4; j++) sv[j] += __shfl_xor_sync(0xffffffffu, sv[j], o);
    }
    if (lane == 0) {
#pragma unroll
        for (int j = 0; j < 4; j++) wred[w8 * 4 + j] = sv[j];
    }
    __syncthreads();
    if (t == 0) {
#pragma unroll
        for (int j = 0; j < 4; j++) {
            float s = 0.f;
#pragma unroll
            for (int w = 0; w < 8; w++) s += wred[w * 4 + j];
            g_part_z[(b * 32 + tile) * 4 + j] = s;
        }
    }
}

// ---------------- K7: (inlined GN-z stats) + seg conv1x1 ----------------
__global__ __launch_bounds__(256) void k7_seg(
    const float* __restrict__ gref, const float* __restrict__ bref,
    const float* __restrict__ Wseg) {
    __shared__ float sa[16], sb[16], sws[16];
    int t = threadIdx.x, b = blockIdx.y;
    int p = blockIdx.x * 256 + t;
    if (t < 32) {
        float l[4];
#pragma unroll
        for (int j = 0; j < 4; j++) {
            float v = g_part_z[(b * 32 + t) * 4 + j];
#pragma unroll
            for (int o = 16; o; o >>= 1) v += __shfl_xor_sync(0xffffffffu, v, o);
            l[j] = v;
        }
        if (t < 16) {
            int g = t >> 3;
            float n = 8.f * HW;
            float m = l[2 * g] / n;
            float r = rsqrtf(l[2 * g + 1] / n - m * m + 1e-5f);
            float a = r * gref[t];
            sa[t] = a; sb[t] = bref[t] - m * a; sws[t] = Wseg[t];
        }
    }
    __syncthreads();
    const float* zb = g_z + (size_t)b * 16 * HW + p;
    float acc = 0.f;
#pragma unroll
    for (int c = 0; c < 16; c++) {
        float zn = zb[c * HW] * sa[c] + sb[c];
        acc += mish_f(zn) * sws[c];
    }
    g_seg[b * HW + p] = acc;
}

// ---------------- K8: bilinear 128->512 + sigmoid ----------------
__global__ __launch_bounds__(256) void k8_up(float4* __restrict__ out) {
    int idx4 = blockIdx.x * 256 + threadIdx.x;
    int idx = idx4 * 4;
    int b = idx >> 18;
    int rem = idx & 262143;
    int oy = rem >> 9, ox0 = rem & 511;
    float sy = (oy + 0.5f) * 0.25f - 0.5f;
    sy = fminf(fmaxf(sy, 0.f), 127.f);
    int y0 = (int)sy;
    float fy = sy - y0;
    int y1 = min(y0 + 1, 127);
    const float* s = g_seg + b * HW;
    const float* r0 = s + y0 * 128;
    const float* r1 = s + y1 * 128;
    float4 o4;
    float res[4];
#pragma unroll
    for (int j = 0; j < 4; j++) {
        int ox = ox0 + j;
        float sx = (ox + 0.5f) * 0.25f - 0.5f;
        sx = fminf(fmaxf(sx, 0.f), 127.f);
        int x0 = (int)sx;
        float fx = sx - x0;
        int x1 = min(x0 + 1, 127);
        float top = r0[x0] + (r0[x1] - r0[x0]) * fx;
        float bot = r1[x0] + (r1[x1] - r1[x0]) * fx;
        float v = top + (bot - top) * fy;
        res[j] = 1.f / (1.f + __expf(-v));
    }
    o4.x = res[0]; o4.y = res[1]; o4.z = res[2]; o4.w = res[3];
    out[idx4] = o4;
}

// ---------------- launch ----------------
extern "C" void kernel_launch(void* const* d_in, const int* in_sizes, int n_in,
                              void* d_out, int out_size) {
    (void)in_sizes; (void)n_in; (void)out_size;
    const float* low  = (const float*)d_in[0];
    const float* high = (const float*)d_in[1];
    const float* Wc0  = (const float*)d_in[2];
    const float* Wc1  = (const float*)d_in[3];
    const float* Wc2  = (const float*)d_in[4];
    const float* gbn  = (const float*)d_in[5];
    const float* bbn  = (const float*)d_in[6];
    const float* Wlow = (const float*)d_in[7];
    const float* glow = (const float*)d_in[8];
    const float* blow = (const float*)d_in[9];
    const float* Wref = (const float*)d_in[10];
    const float* gref = (const float*)d_in[11];
    const float* bref = (const float*)d_in[12];
    const float* Wseg = (const float*)d_in[13];
    float* out = (float*)d_out;

    k1_conv1x1_high<<<dim3(16, 48), 256>>>(high, Wc0);
    k2_branch<<<dim3(32, 48), 256>>>(Wc1, Wc2);
    k3_low<<<dim3(16, 48), 256>>>(low, Wlow);
    k5_ref<<<dim3(32, 48), 256>>>(Wref, gbn, bbn, glow, blow);   // launch #4 -> profiled
    k7_seg<<<dim3(64, 48), 256>>>(gref, bref, Wseg);
    k8_up<<<12288, 256>>>((float4*)out);
}

// round 14
// speedup vs baseline: 1.3681x; 1.0633x over previous
#include <cuda_runtime.h>

#define BATCH 48
#define HH 128
#define WW 128
#define HW 16384

// ---------------- scratch (device globals; no allocation) ----------------
__device__ float g_in0[BATCH * 16 * HW];   // conv1x1(high) output
__device__ float g_v[BATCH * 16 * HW];     // branch conv output (pre-GN "high")
__device__ float g_u[BATCH * 16 * HW];     // conv1x1(low) output (pre-GN "low")
__device__ float g_z[BATCH * 16 * HW];     // ref conv output (pre-GN)
__device__ float g_seg[BATCH * HW];        // seg logits at 128x128
__device__ float g_part_high[BATCH * 32 * 2];
__device__ float g_part_low[BATCH * 16 * 4];
__device__ float g_part_z[BATCH * 32 * 4];

__device__ __forceinline__ float mish_f(float x) {
    if (x > 20.f) return x;
    float e = __expf(x);
    float n = e * (e + 2.f);
    return x * n / (n + 2.f);
}

__device__ __forceinline__ float tf32r(float x) {
    unsigned u;
    asm("cvt.rna.tf32.f32 %0, %1;" : "=r"(u) : "f"(x));
    return __uint_as_float(u);
}

// m16n8k8 tf32 mma, fp32 accumulate (row.col)
__device__ __forceinline__ void mma8(float& d0, float& d1, float& d2, float& d3,
                                     float a0, float a1, float a2, float a3,
                                     float b0, float b1) {
    asm("mma.sync.aligned.m16n8k8.row.col.f32.tf32.tf32.f32 "
        "{%0,%1,%2,%3}, {%4,%5,%6,%7}, {%8,%9}, {%0,%1,%2,%3};"
        : "+f"(d0), "+f"(d1), "+f"(d2), "+f"(d3)
        : "r"(__float_as_uint(a0)), "r"(__float_as_uint(a1)),
          "r"(__float_as_uint(a2)), "r"(__float_as_uint(a3)),
          "r"(__float_as_uint(b0)), "r"(__float_as_uint(b1)));
}

// ---------------- K1: in0 = conv1x1(high, Wc0)  (32 -> 16) ----------------
__global__ __launch_bounds__(256) void k1_conv1x1_high(
    const float* __restrict__ high, const float* __restrict__ Wc0) {
    __shared__ float sw[512];
    int t = threadIdx.x;
    for (int i = t; i < 512; i += 256) sw[i] = Wc0[i];
    __syncthreads();
    int b = blockIdx.y;
    int p0 = blockIdx.x * 1024;
    const float* hb = high + (size_t)b * 32 * HW + p0 + t;
    float* ob = g_in0 + (size_t)b * 16 * HW + p0 + t;
    float acc[4][16];
#pragma unroll
    for (int i = 0; i < 4; i++)
#pragma unroll
        for (int o = 0; o < 16; o++) acc[i][o] = 0.f;
    for (int c = 0; c < 32; c++) {
        float x0 = hb[c * HW], x1 = hb[c * HW + 256];
        float x2 = hb[c * HW + 512], x3 = hb[c * HW + 768];
#pragma unroll
        for (int o = 0; o < 16; o++) {
            float w = sw[o * 32 + c];
            acc[0][o] += x0 * w; acc[1][o] += x1 * w;
            acc[2][o] += x2 * w; acc[3][o] += x3 * w;
        }
    }
#pragma unroll
    for (int o = 0; o < 16; o++) {
        ob[o * HW] = acc[0][o]; ob[o * HW + 256] = acc[1][o];
        ob[o * HW + 512] = acc[2][o]; ob[o * HW + 768] = acc[3][o];
    }
}

// ---------------- K2: branch convs via tf32 mma, 8 warps / tile ----------
__global__ __launch_bounds__(256, 4) void k2_branch(
    const float* __restrict__ Wc1, const float* __restrict__ Wc2) {
    __shared__ float sx[5760];       // phase1: [8][18][34], phase2: [8][20][36]
    __shared__ float swt[2][8 * 73]; // permuted tf32 weights, pitch 73
    __shared__ float wred[16];
    int t = threadIdx.x;
    int b = blockIdx.y;
    int tile = blockIdx.x;
    int x0 = (tile & 3) * 32, y0 = (tile >> 2) * 16;
    for (int i = t; i < 8 * 73; i += 256) {
        int o = i / 73, j = i - o * 73;
        float w1 = 0.f, w2 = 0.f;
        if (j < 72) {
            int tap = j >> 3, q = j & 7;        // k = tap*8+q  <->  W[o][q][tap]
            w1 = tf32r(Wc1[o * 72 + q * 9 + tap]);
            w2 = tf32r(Wc2[o * 72 + q * 9 + tap]);
        }
        swt[0][i] = w1; swt[1][i] = w2;
    }
    int lane = t & 31, w8 = t >> 5;            // 8 warps, 2 rows each
    int grp = lane >> 2, qid = lane & 3;
    const float* in0b = g_in0 + (size_t)b * 16 * HW;
    float* vb = g_v + (size_t)b * 16 * HW;
    float ls1 = 0.f, ls2 = 0.f;

    // ---- phase 1: channels 0..7, dilation 1, halo 1 (18 x 34) ----
    {
        // decode this thread's 3 positions once (612 = 18*34)
        int pos[3]; int off[3]; bool ok[3]; bool has[3];
#pragma unroll
        for (int j = 0; j < 3; j++) {
            int p = t + j * 256;
            has[j] = (p < 612);
            int pp = has[j] ? p : 0;
            int yy = pp / 34, xx = pp - yy * 34;
            int gy = y0 - 1 + yy, gx = x0 - 1 + xx;
            ok[j] = ((unsigned)gy < 128u) && ((unsigned)gx < 128u);
            off[j] = gy * WW + gx;
            pos[j] = pp;
        }
#pragma unroll 4
        for (int c = 0; c < 8; c++) {
            const float* src = in0b + c * HW;
            float* dst = sx + c * 612;
#pragma unroll
            for (int j = 0; j < 3; j++) {
                if (has[j]) dst[pos[j]] = ok[j] ? tf32r(src[off[j]]) : 0.f;
            }
        }
    }
    __syncthreads();
    {
        float acc[8][2];
        float dz0 = 0.f, dz1 = 0.f;
#pragma unroll
        for (int g = 0; g < 8; g++) { acc[g][0] = 0.f; acc[g][1] = 0.f; }
        const float* pB = sx + w8 * 2 * 34 + grp + qid * 612;
        const float* pW = &swt[0][grp * 73 + qid];
#pragma unroll
        for (int tap = 0; tap < 9; tap++) {
            const int ky = tap / 3, kx = tap - ky * 3;
            const int coff = ky * 34 + kx;
            float a0 = pW[tap * 8];
            float a2 = pW[tap * 8 + 4];
#pragma unroll
            for (int g = 0; g < 8; g++) {
                const int imm = coff + (g >> 2) * 34 + (g & 3) * 8;
                mma8(acc[g][0], acc[g][1], dz0, dz1, a0, 0.f, a2, 0.f,
                     pB[imm], pB[imm + 4 * 612]);
            }
        }
#pragma unroll
        for (int g = 0; g < 8; g++) {
            int gy = y0 + w8 * 2 + (g >> 2);
            int gx = x0 + (g & 3) * 8 + 2 * qid;
            float d0 = acc[g][0], d1 = acc[g][1];
            float2 st; st.x = d0; st.y = d1;
            *(float2*)&vb[grp * HW + gy * WW + gx] = st;
            ls1 += d0 + d1; ls2 += d0 * d0 + d1 * d1;
        }
    }
    __syncthreads();
    // ---- phase 2: channels 8..15, dilation 2, halo 2 (20 x 36) ----
    {
        int pos[3]; int off[3]; bool ok[3]; bool has[3];
#pragma unroll
        for (int j = 0; j < 3; j++) {
            int p = t + j * 256;
            has[j] = (p < 720);
            int pp = has[j] ? p : 0;
            int yy = pp / 36, xx = pp - yy * 36;
            int gy = y0 - 2 + yy, gx = x0 - 2 + xx;
            ok[j] = ((unsigned)gy < 128u) && ((unsigned)gx < 128u);
            off[j] = gy * WW + gx;
            pos[j] = pp;
        }
#pragma unroll 4
        for (int c = 0; c < 8; c++) {
            const float* src = in0b + (c + 8) * HW;
            float* dst = sx + c * 720;
#pragma unroll
            for (int j = 0; j < 3; j++) {
                if (has[j]) dst[pos[j]] = ok[j] ? tf32r(src[off[j]]) : 0.f;
            }
        }
    }
    __syncthreads();
    {
        float acc[8][2];
        float dz0 = 0.f, dz1 = 0.f;
#pragma unroll
        for (int g = 0; g < 8; g++) { acc[g][0] = 0.f; acc[g][1] = 0.f; }
        const float* pB = sx + w8 * 2 * 36 + grp + qid * 720;
        const float* pW = &swt[1][grp * 73 + qid];
#pragma unroll
        for (int tap = 0; tap < 9; tap++) {
            const int ky = tap / 3, kx = tap - ky * 3;
            const int coff = 2 * ky * 36 + 2 * kx;
            float a0 = pW[tap * 8];
            float a2 = pW[tap * 8 + 4];
#pragma unroll
            for (int g = 0; g < 8; g++) {
                const int imm = coff + (g >> 2) * 36 + (g & 3) * 8;
                mma8(acc[g][0], acc[g][1], dz0, dz1, a0, 0.f, a2, 0.f,
                     pB[imm], pB[imm + 4 * 720]);
            }
        }
#pragma unroll
        for (int g = 0; g < 8; g++) {
            int gy = y0 + w8 * 2 + (g >> 2);
            int gx = x0 + (g & 3) * 8 + 2 * qid;
            float d0 = acc[g][0], d1 = acc[g][1];
            float2 st; st.x = d0; st.y = d1;
            *(float2*)&vb[(grp + 8) * HW + gy * WW + gx] = st;
            ls1 += d0 + d1; ls2 += d0 * d0 + d1 * d1;
        }
    }
    // ---- deterministic reduce ----
#pragma unroll
    for (int o = 16; o; o >>= 1) {
        ls1 += __shfl_xor_sync(0xffffffffu, ls1, o);
        ls2 += __shfl_xor_sync(0xffffffffu, ls2, o);
    }
    if (lane == 0) { wred[w8] = ls1; wred[8 + w8] = ls2; }
    __syncthreads();
    if (t == 0) {
        float s1 = 0.f, s2 = 0.f;
#pragma unroll
        for (int w = 0; w < 8; w++) { s1 += wred[w]; s2 += wred[8 + w]; }
        g_part_high[(b * 32 + tile) * 2 + 0] = s1;
        g_part_high[(b * 32 + tile) * 2 + 1] = s2;
    }
}

// ---------------- K3: u = conv1x1(low, Wlow) (24 -> 16), + GN-low partials
__global__ __launch_bounds__(256) void k3_low(
    const float* __restrict__ low, const float* __restrict__ Wlow) {
    __shared__ float sw[384];
    __shared__ float red[256];
    int t = threadIdx.x;
    int b = blockIdx.y;
    int p0 = blockIdx.x * 1024;
    for (int i = t; i < 384; i += 256) sw[i] = Wlow[i];
    __syncthreads();
    const float* lb = low + (size_t)b * 24 * HW + p0 + t;
    float* ub = g_u + (size_t)b * 16 * HW + p0 + t;
    float acc[4][16];
#pragma unroll
    for (int i = 0; i < 4; i++)
#pragma unroll
        for (int o = 0; o < 16; o++) acc[i][o] = 0.f;
    for (int c = 0; c < 24; c++) {
        float x0 = lb[c * HW], x1 = lb[c * HW + 256];
        float x2 = lb[c * HW + 512], x3 = lb[c * HW + 768];
#pragma unroll
        for (int o = 0; o < 16; o++) {
            float w = sw[o * 24 + c];
            acc[0][o] += x0 * w; acc[1][o] += x1 * w;
            acc[2][o] += x2 * w; acc[3][o] += x3 * w;
        }
    }
    float sv[4] = {0.f, 0.f, 0.f, 0.f};
#pragma unroll
    for (int o = 0; o < 16; o++) {
        float v0 = acc[0][o], v1 = acc[1][o], v2 = acc[2][o], v3 = acc[3][o];
        ub[o * HW] = v0; ub[o * HW + 256] = v1;
        ub[o * HW + 512] = v2; ub[o * HW + 768] = v3;
        int g = (o >> 3) * 2;
        sv[g] += v0 + v1 + v2 + v3;
        sv[g + 1] += v0 * v0 + v1 * v1 + v2 * v2 + v3 * v3;
    }
#pragma unroll
    for (int j = 0; j < 4; j++) {
        red[t] = sv[j]; __syncthreads();
        for (int s = 128; s > 0; s >>= 1) { if (t < s) red[t] += red[t + s]; __syncthreads(); }
        if (t == 0) g_part_low[(b * 16 + blockIdx.x) * 4 + j] = red[0];
        __syncthreads();
    }
}

// ---------------- K5: (inlined GN stats) + mish fuse + conv3x3, 8 warps ----
__global__ __launch_bounds__(256, 4) void k5_ref(
    const float* __restrict__ Wref,
    const float* __restrict__ gbn, const float* __restrict__ bbn,
    const float* __restrict__ glow, const float* __restrict__ blow) {
    __shared__ float sr[9792];       // [16][18][34]
    __shared__ float sw5[16 * 145];  // permuted tf32 weights, pitch 145
    __shared__ float sa1[16], sa2[16], sa3[16];
    __shared__ float wred[32];
    int t = threadIdx.x;
    int b = blockIdx.y;
    int tile = blockIdx.x;
    int x0 = (tile & 3) * 32, y0 = (tile >> 2) * 16;
    for (int i = t; i < 16 * 145; i += 256) {
        int o = i / 145, j = i - o * 145;
        float w = 0.f;
        if (j < 144) {
            int c = j >> 3, q = j & 7;           // k = c*8+q
            int tap = c >> 1, half = c & 1;      // ci = half*8+q
            w = tf32r(Wref[o * 144 + (half * 8 + q) * 9 + tap]);
        }
        sw5[i] = w;
    }
    // --- inlined stats: warp 0 reduces partials ---
    if (t < 32) {
        float h1 = g_part_high[(b * 32 + t) * 2 + 0];
        float h2 = g_part_high[(b * 32 + t) * 2 + 1];
#pragma unroll
        for (int o = 16; o; o >>= 1) {
            h1 += __shfl_xor_sync(0xffffffffu, h1, o);
            h2 += __shfl_xor_sync(0xffffffffu, h2, o);
        }
        float l[4];
#pragma unroll
        for (int j = 0; j < 4; j++) {
            float v = (t < 16) ? g_part_low[(b * 16 + t) * 4 + j] : 0.f;
#pragma unroll
            for (int o = 16; o; o >>= 1) v += __shfl_xor_sync(0xffffffffu, v, o);
            l[j] = v;
        }
        if (t < 16) {
            int c = t, g = c >> 3;
            float nH = 16.f * HW, nL = 8.f * HW;
            float mH = h1 / nH;
            float rH = rsqrtf(h2 / nH - mH * mH + 1e-5f);
            float mL = l[2 * g] / nL;
            float rL = rsqrtf(l[2 * g + 1] / nL - mL * mL + 1e-5f);
            float a1 = rH * gbn[c], a2 = rL * glow[c];
            sa1[c] = a1; sa2[c] = a2;
            sa3[c] = bbn[c] + blow[c] - mH * a1 - mL * a2;
        }
    }
    __syncthreads();
    const float* vb = g_v + (size_t)b * 16 * HW;
    const float* ub = g_u + (size_t)b * 16 * HW;
    {
        int pos[3]; int off[3]; bool ok[3]; bool has[3];
#pragma unroll
        for (int j = 0; j < 3; j++) {
            int p = t + j * 256;
            has[j] = (p < 612);
            int pp = has[j] ? p : 0;
            int yy = pp / 34, xx = pp - yy * 34;
            int gy = y0 - 1 + yy, gx = x0 - 1 + xx;
            ok[j] = ((unsigned)gy < 128u) && ((unsigned)gx < 128u);
            off[j] = gy * WW + gx;
            pos[j] = pp;
        }
#pragma unroll 4
        for (int c = 0; c < 16; c++) {
            float a1 = sa1[c], a2 = sa2[c], a3 = sa3[c];
            const float* vc = vb + c * HW;
            const float* uc = ub + c * HW;
            float* dst = sr + c * 612;
#pragma unroll
            for (int j = 0; j < 3; j++) {
                if (has[j]) {
                    float val = 0.f;
                    if (ok[j]) val = mish_f(vc[off[j]] * a1 + uc[off[j]] * a2 + a3);
                    dst[pos[j]] = tf32r(val);
                }
            }
        }
    }
    __syncthreads();
    int lane = t & 31, w8 = t >> 5;            // 8 warps, 2 rows each
    int grp = lane >> 2, qid = lane & 3;
    float acc[8][4];
#pragma unroll
    for (int g = 0; g < 8; g++) {
        acc[g][0] = 0.f; acc[g][1] = 0.f; acc[g][2] = 0.f; acc[g][3] = 0.f;
    }
    const float* pB = sr + w8 * 2 * 34 + grp + qid * 612;
    const float* pW = sw5 + grp * 145 + qid;
#pragma unroll
    for (int c = 0; c < 18; c++) {
        const int tap = c >> 1, half = c & 1;
        const int ky = tap / 3, kx = tap - ky * 3;
        const int coff = half * 8 * 612 + ky * 34 + kx;
        float a0 = pW[c * 8];
        float a2 = pW[c * 8 + 4];
        float a1 = pW[c * 8 + 8 * 145];
        float a3 = pW[c * 8 + 8 * 145 + 4];
#pragma unroll
        for (int g = 0; g < 8; g++) {
            const int imm = coff + (g >> 2) * 34 + (g & 3) * 8;
            mma8(acc[g][0], acc[g][1], acc[g][2], acc[g][3],
                 a0, a1, a2, a3, pB[imm], pB[imm + 4 * 612]);
        }
    }
    float* zb = g_z + (size_t)b * 16 * HW;
    float sv[4] = {0.f, 0.f, 0.f, 0.f};
#pragma unroll
    for (int g = 0; g < 8; g++) {
        int gy = y0 + w8 * 2 + (g >> 2);
        int gx = x0 + (g & 3) * 8 + 2 * qid;
        float d0 = acc[g][0], d1 = acc[g][1], d2 = acc[g][2], d3 = acc[g][3];
        float2 s0; s0.x = d0; s0.y = d1;
        float2 s1; s1.x = d2; s1.y = d3;
        *(float2*)&zb[grp * HW + gy * WW + gx] = s0;
        *(float2*)&zb[(grp + 8) * HW + gy * WW + gx] = s1;
        sv[0] += d0 + d1; sv[1] += d0 * d0 + d1 * d1;
        sv[2] += d2 + d3; sv[3] += d2 * d2 + d3 * d3;
    }
#pragma unroll
    for (int o = 16; o; o >>= 1) {
#pragma unroll
        for (int j = 0; j < 4; j++) sv[j] += __shfl_xor_sync(0xffffffffu, sv[j], o);
    }
    if (lane == 0) {
#pragma unroll
        for (int j = 0; j < 4; j++) wred[w8 * 4 + j] = sv[j];
    }
    __syncthreads();
    if (t == 0) {
#pragma unroll
        for (int j = 0; j < 4; j++) {
            float s = 0.f;
#pragma unroll
            for (int w = 0; w < 8; w++) s += wred[w * 4 + j];
            g_part_z[(b * 32 + tile) * 4 + j] = s;
        }
    }
}

// ---------------- K7: (inlined GN-z stats) + seg conv1x1 (float4) --------
__global__ __launch_bounds__(256) void k7_seg(
    const float* __restrict__ gref, const float* __restrict__ bref,
    const float* __restrict__ Wseg) {
    __shared__ float sa[16], sb[16], sws[16];
    int t = threadIdx.x, b = blockIdx.y;
    int p4 = blockIdx.x * 256 + t;        // float4 index, 4096 per batch
    if (t < 32) {
        float l[4];
#pragma unroll
        for (int j = 0; j < 4; j++) {
            float v = g_part_z[(b * 32 + t) * 4 + j];
#pragma unroll
            for (int o = 16; o; o >>= 1) v += __shfl_xor_sync(0xffffffffu, v, o);
            l[j] = v;
        }
        if (t < 16) {
            int g = t >> 3;
            float n = 8.f * HW;
            float m = l[2 * g] / n;
            float r = rsqrtf(l[2 * g + 1] / n - m * m + 1e-5f);
            float a = r * gref[t];
            sa[t] = a; sb[t] = bref[t] - m * a; sws[t] = Wseg[t];
        }
    }
    __syncthreads();
    const float4* zb4 = (const float4*)(g_z + (size_t)b * 16 * HW) + p4;
    float a0 = 0.f, a1 = 0.f, a2 = 0.f, a3 = 0.f;
#pragma unroll
    for (int c = 0; c < 16; c++) {
        float4 z = zb4[c * 4096];
        float sc = sa[c], sh = sb[c], w = sws[c];
        a0 += mish_f(z.x * sc + sh) * w;
        a1 += mish_f(z.y * sc + sh) * w;
        a2 += mish_f(z.z * sc + sh) * w;
        a3 += mish_f(z.w * sc + sh) * w;
    }
    float4 o4; o4.x = a0; o4.y = a1; o4.z = a2; o4.w = a3;
    ((float4*)(g_seg + (size_t)b * HW))[p4] = o4;
}

// ---------------- K8: bilinear 128->512 + sigmoid ----------------
__global__ __launch_bounds__(256) void k8_up(float4* __restrict__ out) {
    int idx4 = blockIdx.x * 256 + threadIdx.x;
    int idx = idx4 * 4;
    int b = idx >> 18;
    int rem = idx & 262143;
    int oy = rem >> 9, ox0 = rem & 511;
    float sy = (oy + 0.5f) * 0.25f - 0.5f;
    sy = fminf(fmaxf(sy, 0.f), 127.f);
    int y0 = (int)sy;
    float fy = sy - y0;
    int y1 = min(y0 + 1, 127);
    const float* s = g_seg + b * HW;
    const float* r0 = s + y0 * 128;
    const float* r1 = s + y1 * 128;
    float4 o4;
    float res[4];
#pragma unroll
    for (int j = 0; j < 4; j++) {
        int ox = ox0 + j;
        float sx = (ox + 0.5f) * 0.25f - 0.5f;
        sx = fminf(fmaxf(sx, 0.f), 127.f);
        int x0 = (int)sx;
        float fx = sx - x0;
        int x1 = min(x0 + 1, 127);
        float top = r0[x0] + (r0[x1] - r0[x0]) * fx;
        float bot = r1[x0] + (r1[x1] - r1[x0]) * fx;
        float v = top + (bot - top) * fy;
        res[j] = 1.f / (1.f + __expf(-v));
    }
    o4.x = res[0]; o4.y = res[1]; o4.z = res[2]; o4.w = res[3];
    out[idx4] = o4;
}

// ---------------- launch ----------------
extern "C" void kernel_launch(void* const* d_in, const int* in_sizes, int n_in,
                              void* d_out, int out_size) {
    (void)in_sizes; (void)n_in; (void)out_size;
    const float* low  = (const float*)d_in[0];
    const float* high = (const float*)d_in[1];
    const float* Wc0  = (const float*)d_in[2];
    const float* Wc1  = (const float*)d_in[3];
    const float* Wc2  = (const float*)d_in[4];
    const float* gbn  = (const float*)d_in[5];
    const float* bbn  = (const float*)d_in[6];
    const float* Wlow = (const float*)d_in[7];
    const float* glow = (const float*)d_in[8];
    const float* blow = (const float*)d_in[9];
    const float* Wref = (const float*)d_in[10];
    const float* gref = (const float*)d_in[11];
    const float* bref = (const float*)d_in[12];
    const float* Wseg = (const float*)d_in[13];
    float* out = (float*)d_out;

    k1_conv1x1_high<<<dim3(16, 48), 256>>>(high, Wc0);
    k2_branch<<<dim3(32, 48), 256>>>(Wc1, Wc2);
    k3_low<<<dim3(16, 48), 256>>>(low, Wlow);
    k5_ref<<<dim3(32, 48), 256>>>(Wref, gbn, bbn, glow, blow);   // launch #4 -> profiled
    k7_seg<<<dim3(16, 48), 256>>>(gref, bref, Wseg);
    k8_up<<<12288, 256>>>((float4*)out);
}